// round 2
// baseline (speedup 1.0000x reference)
#include <cuda_runtime.h>
#include <cuda_bf16.h>
#include <math.h>

// ---------------------------------------------------------------------------
// CotLayer: B=16, DIM=256, H=W=56, K=3, SP=8, RADIX=2, ATTN=128, EMB=288
// ---------------------------------------------------------------------------
#define BATCH 16
#define DIM   256
#define HH    56
#define WW    56
#define HWSZ  3136          // 56*56
#define EMB   288
#define ATTN  128
#define GRPS  32            // DIM/SP
#define EPSB  1e-5f

// -------------------- scratch (allocation-free: __device__ globals) --------
__device__ float g_k   [(size_t)BATCH * DIM * HWSZ];   // key embed
__device__ float g_w1  [(size_t)BATCH * 128 * HWSZ];   // embed conv1 out
__device__ float g_w2  [(size_t)BATCH * EMB * HWSZ];   // embed conv2 out (pre-GN)
__device__ float g_xq  [(size_t)BATCH * DIM * HWSZ];   // value branch
__device__ float g_y   [(size_t)BATCH * DIM * HWSZ];   // dynconv out (post swish)
__device__ float g_gn  [BATCH * GRPS * 2];             // groupnorm mean / rstd
__device__ float g_gap [BATCH * DIM];                  // global average pool
__device__ float g_att [BATCH * DIM * 2];              // softmax attention

// ---------------------------------------------------------------------------
// Generic conv-as-GEMM with implicit im2col + fused epilogue.
// O[b, m, p] = sum_k W[m, k] * X(b, k, p)
//   MODE 0 : 1x1 conv, single input  (k = input channel)
//   MODE 1 : 1x1 conv, concat(X1, X2) at channel Csplit
//   MODE 2 : grouped 3x3 conv, pad 1; BM must equal group out-width (64),
//            input channel = (m0) + k/9, tap = k%9
//   EPI  0 : BatchNorm + ReLU   (p0..p3 = g,b,m,v)
//   EPI  1 : BatchNorm           (p0..p3 = g,b,m,v)
//   EPI  2 : +bias               (p0 = bias)
// ---------------------------------------------------------------------------
template<int BM, int BN, int BK, int TM, int TN, int MODE, int EPI>
__global__ void convgemm(const float* __restrict__ Wt,
                         const float* __restrict__ X1,
                         const float* __restrict__ X2,
                         float* __restrict__ Out,
                         int M, int Ktot, int XC, int Csplit,
                         const float* __restrict__ p0,
                         const float* __restrict__ p1,
                         const float* __restrict__ p2,
                         const float* __restrict__ p3)
{
    constexpr int NT = (BM / TM) * (BN / TN);
    const int b   = blockIdx.z;
    const int m0  = blockIdx.x * BM;
    const int n0  = blockIdx.y * BN;
    const int tid = threadIdx.x;
    const int tx  = tid % (BN / TN);
    const int ty  = tid / (BN / TN);
    const int cbase = (MODE == 2) ? m0 : 0;   // group base channel (BM==64)

    __shared__ float As[BK][BM];
    __shared__ float Bs[BK][BN];

    float acc[TM][TN];
#pragma unroll
    for (int i = 0; i < TM; i++)
#pragma unroll
        for (int j = 0; j < TN; j++) acc[i][j] = 0.f;

    for (int k0 = 0; k0 < Ktot; k0 += BK) {
        // ---- load W tile : As[k][m]
#pragma unroll
        for (int i = 0; i < (BM * BK) / NT; i++) {
            int a = tid + i * NT;
            int m = a % BM, kk = a / BM;
            int gm = m0 + m, gk = k0 + kk;
            float v = 0.f;
            if (gm < M) v = Wt[(size_t)gm * Ktot + gk];
            As[kk][m] = v;
        }
        // ---- load X tile : Bs[k][n]
#pragma unroll
        for (int i = 0; i < (BN * BK) / NT; i++) {
            int a = tid + i * NT;
            int n = a % BN, kk = a / BN;
            int gn = n0 + n, gk = k0 + kk;
            float v = 0.f;
            if (gn < HWSZ) {
                if (MODE == 0) {
                    v = X1[((size_t)b * XC + gk) * HWSZ + gn];
                } else if (MODE == 1) {
                    if (gk < Csplit)
                        v = X1[((size_t)b * Csplit + gk) * HWSZ + gn];
                    else
                        v = X2[((size_t)b * (XC - Csplit) + (gk - Csplit)) * HWSZ + gn];
                } else {  // MODE 2: grouped 3x3, pad 1
                    int ci = gk / 9, t = gk % 9;
                    int dh = t / 3 - 1, dw = t % 3 - 1;
                    int h = gn / WW + dh, w = gn % WW + dw;
                    if ((unsigned)h < (unsigned)HH && (unsigned)w < (unsigned)WW)
                        v = X1[((size_t)b * XC + cbase + ci) * HWSZ + h * WW + w];
                }
            }
            Bs[kk][n] = v;
        }
        __syncthreads();

#pragma unroll
        for (int kk = 0; kk < BK; kk++) {
            float ra[TM], rb[TN];
#pragma unroll
            for (int i = 0; i < TM; i++) ra[i] = As[kk][ty * TM + i];
#pragma unroll
            for (int j = 0; j < TN; j++) rb[j] = Bs[kk][tx * TN + j];
#pragma unroll
            for (int i = 0; i < TM; i++)
#pragma unroll
                for (int j = 0; j < TN; j++) acc[i][j] += ra[i] * rb[j];
        }
        __syncthreads();
    }

    // ---- epilogue
#pragma unroll
    for (int i = 0; i < TM; i++) {
        int gm = m0 + ty * TM + i;
        if (gm >= M) continue;
        float sc, sh;
        if (EPI <= 1) {
            sc = p0[gm] * rsqrtf(p3[gm] + EPSB);
            sh = p1[gm] - p2[gm] * sc;
        } else {
            sc = 1.f; sh = p0[gm];
        }
#pragma unroll
        for (int j = 0; j < TN; j++) {
            int gn = n0 + tx * TN + j;
            if (gn >= HWSZ) continue;
            float v = acc[i][j] * sc + sh;
            if (EPI == 0) v = fmaxf(v, 0.f);
            Out[((size_t)b * M + gm) * HWSZ + gn] = v;
        }
    }
}

// ---------------------------------------------------------------------------
// GroupNorm statistics over (b, group): 9 contiguous channels * 3136 pixels
// ---------------------------------------------------------------------------
__global__ void gn_stats_kernel(const float* __restrict__ w2, float* __restrict__ stat)
{
    const int g = blockIdx.x, b = blockIdx.y;
    const size_t base = ((size_t)b * EMB + g * 9) * HWSZ;
    const int n = 9 * HWSZ;

    float s = 0.f, sq = 0.f;
    for (int i = threadIdx.x; i < n; i += blockDim.x) {
        float v = w2[base + i];
        s += v; sq += v * v;
    }
    __shared__ float sh_s[256], sh_q[256];
    sh_s[threadIdx.x] = s; sh_q[threadIdx.x] = sq;
    __syncthreads();
    for (int off = 128; off > 0; off >>= 1) {
        if (threadIdx.x < off) {
            sh_s[threadIdx.x] += sh_s[threadIdx.x + off];
            sh_q[threadIdx.x] += sh_q[threadIdx.x + off];
        }
        __syncthreads();
    }
    if (threadIdx.x == 0) {
        float mean = sh_s[0] / (float)n;
        float var  = sh_q[0] / (float)n - mean * mean;
        stat[(b * GRPS + g) * 2 + 0] = mean;
        stat[(b * GRPS + g) * 2 + 1] = rsqrtf(var + EPSB);
    }
}

// ---------------------------------------------------------------------------
// Dynamic local 3x3 conv: y[b,c,p] = sum_t xq[b,c,p+d(t)] * wn[b, (c/8)*9+t, p]
// wn = GroupNorm-normalized w2. Then BN(b2) + swish.
// ---------------------------------------------------------------------------
__global__ void dynconv_kernel(const float* __restrict__ xq,
                               const float* __restrict__ w2,
                               const float* __restrict__ stat,
                               const float* __restrict__ gng,
                               const float* __restrict__ gnb,
                               const float* __restrict__ b2g,
                               const float* __restrict__ b2b,
                               const float* __restrict__ b2m,
                               const float* __restrict__ b2v,
                               float* __restrict__ y)
{
    const int b = blockIdx.z, g = blockIdx.y;
    const int p = blockIdx.x * blockDim.x + threadIdx.x;
    if (p >= HWSZ) return;
    const int h = p / WW, w = p % WW;

    const float mean = stat[(b * GRPS + g) * 2 + 0];
    const float rstd = stat[(b * GRPS + g) * 2 + 1];

    float wn[9];
#pragma unroll
    for (int t = 0; t < 9; t++) {
        int ch = g * 9 + t;
        float v = w2[((size_t)b * EMB + ch) * HWSZ + p];
        wn[t] = (v - mean) * rstd * gng[ch] + gnb[ch];
    }

#pragma unroll
    for (int s = 0; s < 8; s++) {
        int c = g * 8 + s;
        const float* xp = xq + ((size_t)b * DIM + c) * HWSZ;
        float acc = 0.f;
#pragma unroll
        for (int t = 0; t < 9; t++) {
            int hh = h + t / 3 - 1, ww2 = w + t % 3 - 1;
            if ((unsigned)hh < (unsigned)HH && (unsigned)ww2 < (unsigned)WW)
                acc += xp[hh * WW + ww2] * wn[t];
        }
        float sc = b2g[c] * rsqrtf(b2v[c] + EPSB);
        float v = acc * sc + (b2b[c] - b2m[c] * sc);
        v = v / (1.f + expf(-v));                      // swish
        y[((size_t)b * DIM + c) * HWSZ + p] = v;
    }
}

// ---------------------------------------------------------------------------
// Global average pool of (y + k) per (b, c)
// ---------------------------------------------------------------------------
__global__ void gap_kernel(const float* __restrict__ y, const float* __restrict__ k,
                           float* __restrict__ gap)
{
    const int c = blockIdx.x, b = blockIdx.y;
    const size_t base = ((size_t)b * DIM + c) * HWSZ;
    float s = 0.f;
    for (int i = threadIdx.x; i < HWSZ; i += blockDim.x)
        s += y[base + i] + k[base + i];
    __shared__ float sh[256];
    sh[threadIdx.x] = s;
    __syncthreads();
    for (int off = 128; off > 0; off >>= 1) {
        if (threadIdx.x < off) sh[threadIdx.x] += sh[threadIdx.x + off];
        __syncthreads();
    }
    if (threadIdx.x == 0) gap[b * DIM + c] = sh[0] / (float)HWSZ;
}

// ---------------------------------------------------------------------------
// Split-attention head: s1 GEMV + BN + ReLU -> s2 GEMV -> pairwise softmax
// ---------------------------------------------------------------------------
__global__ void attn_kernel(const float* __restrict__ gap,
                            const float* __restrict__ s1w, const float* __restrict__ s1b,
                            const float* __restrict__ s1g, const float* __restrict__ s1bb,
                            const float* __restrict__ s1m, const float* __restrict__ s1v,
                            const float* __restrict__ s2w, const float* __restrict__ s2b,
                            float* __restrict__ att)
{
    const int b = blockIdx.x;
    const int tid = threadIdx.x;
    __shared__ float sg[DIM];
    __shared__ float sa[ATTN];

    sg[tid] = gap[b * DIM + tid];
    __syncthreads();

    if (tid < ATTN) {
        float d = 0.f;
#pragma unroll 8
        for (int j = 0; j < DIM; j++) d += s1w[tid * DIM + j] * sg[j];
        d += s1b[tid];
        float sc = s1g[tid] * rsqrtf(s1v[tid] + EPSB);
        d = d * sc + (s1bb[tid] - s1m[tid] * sc);
        sa[tid] = fmaxf(d, 0.f);
    }
    __syncthreads();

    // tid = channel c in [0, 256)
    float d0 = 0.f, d1 = 0.f;
#pragma unroll 8
    for (int j = 0; j < ATTN; j++) {
        float a = sa[j];
        d0 += s2w[(2 * tid + 0) * ATTN + j] * a;
        d1 += s2w[(2 * tid + 1) * ATTN + j] * a;
    }
    d0 += s2b[2 * tid + 0];
    d1 += s2b[2 * tid + 1];
    float mx = fmaxf(d0, d1);
    float e0 = expf(d0 - mx), e1 = expf(d1 - mx);
    float inv = 1.f / (e0 + e1);
    att[(b * DIM + tid) * 2 + 0] = e0 * inv;
    att[(b * DIM + tid) * 2 + 1] = e1 * inv;
}

// ---------------------------------------------------------------------------
// out = y * a0 + k * a1
// ---------------------------------------------------------------------------
__global__ void out_kernel(const float* __restrict__ y, const float* __restrict__ k,
                           const float* __restrict__ att, float* __restrict__ out)
{
    size_t idx = (size_t)blockIdx.x * blockDim.x + threadIdx.x;
    if (idx >= (size_t)BATCH * DIM * HWSZ) return;
    int bc = (int)(idx / HWSZ);
    float a0 = att[bc * 2 + 0];
    float a1 = att[bc * 2 + 1];
    out[idx] = y[idx] * a0 + k[idx] * a1;
}

// ---------------------------------------------------------------------------
extern "C" void kernel_launch(void* const* d_in, const int* in_sizes, int n_in,
                              void* d_out, int out_size)
{
    const float* x    = (const float*)d_in[0];
    const float* ke_w = (const float*)d_in[1];
    const float* ke_g = (const float*)d_in[2];
    const float* ke_b = (const float*)d_in[3];
    const float* ke_m = (const float*)d_in[4];
    const float* ke_v = (const float*)d_in[5];
    const float* e1_w = (const float*)d_in[6];
    const float* e1_g = (const float*)d_in[7];
    const float* e1_b = (const float*)d_in[8];
    const float* e1_m = (const float*)d_in[9];
    const float* e1_v = (const float*)d_in[10];
    const float* e2_w = (const float*)d_in[11];
    const float* e2_b = (const float*)d_in[12];
    const float* gng  = (const float*)d_in[13];
    const float* gnb  = (const float*)d_in[14];
    const float* c1_w = (const float*)d_in[15];
    const float* c1_g = (const float*)d_in[16];
    const float* c1_b = (const float*)d_in[17];
    const float* c1_m = (const float*)d_in[18];
    const float* c1_v = (const float*)d_in[19];
    const float* b2_g = (const float*)d_in[20];
    const float* b2_b = (const float*)d_in[21];
    const float* b2_m = (const float*)d_in[22];
    const float* b2_v = (const float*)d_in[23];
    const float* s1_w = (const float*)d_in[24];
    const float* s1_b = (const float*)d_in[25];
    const float* s1_g = (const float*)d_in[26];
    const float* s1bb = (const float*)d_in[27];
    const float* s1_m = (const float*)d_in[28];
    const float* s1_v = (const float*)d_in[29];
    const float* s2_w = (const float*)d_in[30];
    const float* s2_b = (const float*)d_in[31];
    float* out = (float*)d_out;

    float *k_, *w1_, *w2_, *xq_, *y_, *gn_, *gap_, *att_;
    cudaGetSymbolAddress((void**)&k_,   g_k);
    cudaGetSymbolAddress((void**)&w1_,  g_w1);
    cudaGetSymbolAddress((void**)&w2_,  g_w2);
    cudaGetSymbolAddress((void**)&xq_,  g_xq);
    cudaGetSymbolAddress((void**)&y_,   g_y);
    cudaGetSymbolAddress((void**)&gn_,  g_gn);
    cudaGetSymbolAddress((void**)&gap_, g_gap);
    cudaGetSymbolAddress((void**)&att_, g_att);

    const int NTILES = (HWSZ + 127) / 128;   // 25

    // 1) key embed: grouped 3x3 conv + BN + ReLU  -> g_k
    convgemm<64, 128, 8, 4, 8, 2, 0><<<dim3(4, NTILES, BATCH), 256>>>(
        ke_w, x, nullptr, k_, DIM, 576, DIM, 0, ke_g, ke_b, ke_m, ke_v);

    // 2) w1 = ReLU(BN(e1 . concat(x, k)))  -> g_w1
    convgemm<128, 128, 8, 8, 8, 1, 0><<<dim3(1, NTILES, BATCH), 256>>>(
        e1_w, x, k_, w1_, 128, 512, 512, 256, e1_g, e1_b, e1_m, e1_v);

    // 3) w2 = e2 . w1 + bias  -> g_w2
    convgemm<128, 128, 8, 8, 8, 0, 2><<<dim3(3, NTILES, BATCH), 256>>>(
        e2_w, w1_, nullptr, w2_, EMB, 128, 128, 0, e2_b, nullptr, nullptr, nullptr);

    // 4) GroupNorm stats
    gn_stats_kernel<<<dim3(GRPS, BATCH), 256>>>(w2_, gn_);

    // 5) xq = BN(c1 . x)  -> g_xq
    convgemm<128, 128, 8, 8, 8, 0, 1><<<dim3(2, NTILES, BATCH), 256>>>(
        c1_w, x, nullptr, xq_, DIM, DIM, DIM, 0, c1_g, c1_b, c1_m, c1_v);

    // 6) dynamic conv + BN + swish -> g_y
    dynconv_kernel<<<dim3((HWSZ + 255) / 256, GRPS, BATCH), 256>>>(
        xq_, w2_, gn_, gng, gnb, b2_g, b2_b, b2_m, b2_v, y_);

    // 7) gap = mean(y + k)
    gap_kernel<<<dim3(DIM, BATCH), 256>>>(y_, k_, gap_);

    // 8) split attention
    attn_kernel<<<BATCH, DIM>>>(gap_, s1_w, s1_b, s1_g, s1bb, s1_m, s1_v,
                                s2_w, s2_b, att_);

    // 9) out = y*a0 + k*a1
    size_t total = (size_t)BATCH * DIM * HWSZ;
    out_kernel<<<(unsigned)((total + 255) / 256), 256>>>(y_, k_, att_, out);
}

// round 3
// speedup vs baseline: 2.2632x; 2.2632x over previous
#include <cuda_runtime.h>
#include <cuda_bf16.h>
#include <math.h>
#include <stdint.h>

// ---------------------------------------------------------------------------
// CotLayer: B=16, DIM=256, H=W=56, K=3, SP=8, RADIX=2, ATTN=128, EMB=288
// ---------------------------------------------------------------------------
#define BATCH 16
#define DIM   256
#define HH    56
#define WW    56
#define HWSZ  3136          // 56*56
#define EMB   288
#define ATTN  128
#define GRPS  32            // DIM/SP
#define EPSB  1e-5f

// -------------------- scratch (allocation-free: __device__ globals) --------
__device__ float g_k   [(size_t)BATCH * DIM * HWSZ];   // key embed
__device__ float g_w1  [(size_t)BATCH * 128 * HWSZ];   // embed conv1 out
__device__ float g_w2  [(size_t)BATCH * EMB * HWSZ];   // embed conv2 out (pre-GN)
__device__ float g_xq  [(size_t)BATCH * DIM * HWSZ];   // value branch
__device__ float g_y   [(size_t)BATCH * DIM * HWSZ];   // dynconv out (post swish)
__device__ float g_gn  [BATCH * GRPS * 2];             // groupnorm mean / rstd
__device__ float g_gap [BATCH * DIM];                  // global average pool
__device__ float g_att [BATCH * DIM * 2];              // softmax attention

// ---------------------------------------------------------------------------
__device__ __forceinline__ uint32_t f2tf32(float v) {
    uint32_t u;
    asm("cvt.rna.tf32.f32 %0, %1;" : "=r"(u) : "f"(v));
    return u;
}

__device__ __forceinline__ void mma_tf32(float* c, const uint32_t* a, const uint32_t* b) {
    asm volatile(
        "mma.sync.aligned.m16n8k8.row.col.f32.tf32.tf32.f32 "
        "{%0,%1,%2,%3}, {%4,%5,%6,%7}, {%8,%9}, {%0,%1,%2,%3};\n"
        : "+f"(c[0]), "+f"(c[1]), "+f"(c[2]), "+f"(c[3])
        : "r"(a[0]), "r"(a[1]), "r"(a[2]), "r"(a[3]), "r"(b[0]), "r"(b[1]));
}

// ---------------------------------------------------------------------------
// Tensor-core conv-as-GEMM (tf32 mma.sync) with implicit im2col + epilogue.
// O[b, m, p] = sum_k W[m, k] * X(b, k, p)
//   MODE 0 : 1x1 conv, single input
//   MODE 1 : 1x1 conv, concat(X1, X2) at channel Csplit
//   MODE 2 : grouped 3x3 conv pad 1; BM==64 per group, group = blockIdx.x
//   EPI  0 : BN + ReLU   EPI 1 : BN   EPI 2 : +bias
// Block: 256 threads = 8 warps laid out (BM/WM) x (BN/WN). BK = 16.
// ---------------------------------------------------------------------------
template<int BM, int BN, int WM, int WN, int MODE, int EPI>
__global__ void __launch_bounds__(256)
convmma(const float* __restrict__ Wt,
        const float* __restrict__ X1,
        const float* __restrict__ X2,
        float* __restrict__ Out,
        int M, int Ktot, int XC, int Csplit,
        const float* __restrict__ p0,
        const float* __restrict__ p1,
        const float* __restrict__ p2,
        const float* __restrict__ p3)
{
    constexpr int BK = 16;
    constexpr int WARPS_N = BN / WN;
    constexpr int MT = WM / 16;           // m-tiles per warp
    constexpr int NT = WN / 8;            // n-tiles per warp

    const int b   = blockIdx.z;
    const int m0  = blockIdx.x * BM;
    const int n0  = blockIdx.y * BN;
    const int tid = threadIdx.x;
    const int wid = tid >> 5;
    const int lane = tid & 31;
    const int grp = lane >> 2;            // 0..7
    const int tg  = lane & 3;             // 0..3
    const int warp_m = wid / WARPS_N;
    const int warp_n = wid % WARPS_N;

    __shared__ uint32_t As[BK][BM + 4];
    __shared__ uint32_t Bs[BK][BN + 4];

    float acc[MT][NT][4];
#pragma unroll
    for (int i = 0; i < MT; i++)
#pragma unroll
        for (int j = 0; j < NT; j++)
#pragma unroll
            for (int q = 0; q < 4; q++) acc[i][j][q] = 0.f;

    for (int k0 = 0; k0 < Ktot; k0 += BK) {
        // ---- A tile: W[m][k] -> As[k][m], float4 along k, cvt to tf32
#pragma unroll
        for (int it = 0; it < (BM * BK) / (4 * 256); it++) {
            int idx = tid + it * 256;             // over BM * (BK/4)
            int m  = idx >> 2;                    // /(BK/4)
            int kq = idx & 3;
            int gm = m0 + m, gk = k0 + kq * 4;
            float4 v = make_float4(0.f, 0.f, 0.f, 0.f);
            if (gm < M) v = *(const float4*)(Wt + (size_t)gm * Ktot + gk);
            As[kq * 4 + 0][m] = f2tf32(v.x);
            As[kq * 4 + 1][m] = f2tf32(v.y);
            As[kq * 4 + 2][m] = f2tf32(v.z);
            As[kq * 4 + 3][m] = f2tf32(v.w);
        }
        // ---- B tile: X(k, n) -> Bs[k][n]
        if (MODE != 2) {
#pragma unroll
            for (int it = 0; it < (BN * BK) / (4 * 256); it++) {
                int idx = tid + it * 256;         // over (BN/4) * BK
                int n4 = idx % (BN / 4);
                int kk = idx / (BN / 4);
                int gn = n0 + n4 * 4, gk = k0 + kk;
                float4 v = make_float4(0.f, 0.f, 0.f, 0.f);
                if (gn + 3 < HWSZ) {
                    const float* src;
                    if (MODE == 0 || gk < Csplit)
                        src = X1 + ((size_t)b * (MODE == 1 ? Csplit : XC) + gk) * HWSZ + gn;
                    else
                        src = X2 + ((size_t)b * (XC - Csplit) + (gk - Csplit)) * HWSZ + gn;
                    v = *(const float4*)src;
                }
                Bs[kk][n4 * 4 + 0] = f2tf32(v.x);
                Bs[kk][n4 * 4 + 1] = f2tf32(v.y);
                Bs[kk][n4 * 4 + 2] = f2tf32(v.z);
                Bs[kk][n4 * 4 + 3] = f2tf32(v.w);
            }
        } else {
            // grouped 3x3 im2col gather (scalar)
#pragma unroll
            for (int it = 0; it < (BN * BK) / 256; it++) {
                int idx = tid + it * 256;
                int n  = idx % BN;
                int kk = idx / BN;
                int gn = n0 + n, gk = k0 + kk;
                float v = 0.f;
                if (gn < HWSZ) {
                    int ci = gk / 9, t = gk % 9;
                    int h = gn / WW + t / 3 - 1;
                    int w = gn % WW + t % 3 - 1;
                    if ((unsigned)h < (unsigned)HH && (unsigned)w < (unsigned)WW)
                        v = X1[((size_t)b * XC + m0 + ci) * HWSZ + h * WW + w];
                }
                Bs[kk][n] = f2tf32(v);
            }
        }
        __syncthreads();

#pragma unroll
        for (int ks = 0; ks < BK; ks += 8) {
            uint32_t af[MT][4];
            uint32_t bf[NT][2];
#pragma unroll
            for (int i = 0; i < MT; i++) {
                int m = warp_m * WM + i * 16 + grp;
                af[i][0] = As[ks + tg    ][m];
                af[i][1] = As[ks + tg    ][m + 8];
                af[i][2] = As[ks + tg + 4][m];
                af[i][3] = As[ks + tg + 4][m + 8];
            }
#pragma unroll
            for (int j = 0; j < NT; j++) {
                int n = warp_n * WN + j * 8 + grp;
                bf[j][0] = Bs[ks + tg    ][n];
                bf[j][1] = Bs[ks + tg + 4][n];
            }
#pragma unroll
            for (int i = 0; i < MT; i++)
#pragma unroll
                for (int j = 0; j < NT; j++)
                    mma_tf32(acc[i][j], af[i], bf[j]);
        }
        __syncthreads();
    }

    // ---- epilogue: rows grp and grp+8 per m-tile, paired cols 2*tg, 2*tg+1
#pragma unroll
    for (int i = 0; i < MT; i++) {
        int r0 = m0 + warp_m * WM + i * 16 + grp;
        int r1 = r0 + 8;
        float sc0 = 1.f, sh0 = 0.f, sc1 = 1.f, sh1 = 0.f;
        if (EPI <= 1) {
            if (r0 < M) { sc0 = p0[r0] * rsqrtf(p3[r0] + EPSB); sh0 = p1[r0] - p2[r0] * sc0; }
            if (r1 < M) { sc1 = p0[r1] * rsqrtf(p3[r1] + EPSB); sh1 = p1[r1] - p2[r1] * sc1; }
        } else {
            if (r0 < M) sh0 = p0[r0];
            if (r1 < M) sh1 = p0[r1];
        }
#pragma unroll
        for (int j = 0; j < NT; j++) {
            int n = n0 + warp_n * WN + j * 8 + 2 * tg;
            if (n >= HWSZ) continue;
            float v0 = acc[i][j][0] * sc0 + sh0;
            float v1 = acc[i][j][1] * sc0 + sh0;
            float v2 = acc[i][j][2] * sc1 + sh1;
            float v3 = acc[i][j][3] * sc1 + sh1;
            if (EPI == 0) {
                v0 = fmaxf(v0, 0.f); v1 = fmaxf(v1, 0.f);
                v2 = fmaxf(v2, 0.f); v3 = fmaxf(v3, 0.f);
            }
            if (r0 < M) *(float2*)(Out + ((size_t)b * M + r0) * HWSZ + n) = make_float2(v0, v1);
            if (r1 < M) *(float2*)(Out + ((size_t)b * M + r1) * HWSZ + n) = make_float2(v2, v3);
        }
    }
}

// ---------------------------------------------------------------------------
// GroupNorm statistics over (b, group): 9 contiguous channels * 3136 pixels
// ---------------------------------------------------------------------------
__global__ void gn_stats_kernel(const float* __restrict__ w2, float* __restrict__ stat)
{
    const int g = blockIdx.x, b = blockIdx.y;
    const size_t base = ((size_t)b * EMB + g * 9) * HWSZ;
    const int n = 9 * HWSZ;

    float s = 0.f, sq = 0.f;
    for (int i = threadIdx.x; i < n; i += blockDim.x) {
        float v = w2[base + i];
        s += v; sq += v * v;
    }
    __shared__ float sh_s[256], sh_q[256];
    sh_s[threadIdx.x] = s; sh_q[threadIdx.x] = sq;
    __syncthreads();
    for (int off = 128; off > 0; off >>= 1) {
        if (threadIdx.x < off) {
            sh_s[threadIdx.x] += sh_s[threadIdx.x + off];
            sh_q[threadIdx.x] += sh_q[threadIdx.x + off];
        }
        __syncthreads();
    }
    if (threadIdx.x == 0) {
        float mean = sh_s[0] / (float)n;
        float var  = sh_q[0] / (float)n - mean * mean;
        stat[(b * GRPS + g) * 2 + 0] = mean;
        stat[(b * GRPS + g) * 2 + 1] = rsqrtf(var + EPSB);
    }
}

// ---------------------------------------------------------------------------
// Dynamic local 3x3 conv + BN + swish
// ---------------------------------------------------------------------------
__global__ void dynconv_kernel(const float* __restrict__ xq,
                               const float* __restrict__ w2,
                               const float* __restrict__ stat,
                               const float* __restrict__ gng,
                               const float* __restrict__ gnb,
                               const float* __restrict__ b2g,
                               const float* __restrict__ b2b,
                               const float* __restrict__ b2m,
                               const float* __restrict__ b2v,
                               float* __restrict__ y)
{
    const int b = blockIdx.z, g = blockIdx.y;
    const int p = blockIdx.x * blockDim.x + threadIdx.x;
    if (p >= HWSZ) return;
    const int h = p / WW, w = p % WW;

    const float mean = stat[(b * GRPS + g) * 2 + 0];
    const float rstd = stat[(b * GRPS + g) * 2 + 1];

    float wn[9];
#pragma unroll
    for (int t = 0; t < 9; t++) {
        int ch = g * 9 + t;
        float v = w2[((size_t)b * EMB + ch) * HWSZ + p];
        wn[t] = (v - mean) * rstd * gng[ch] + gnb[ch];
    }

#pragma unroll
    for (int s = 0; s < 8; s++) {
        int c = g * 8 + s;
        const float* xp = xq + ((size_t)b * DIM + c) * HWSZ;
        float acc = 0.f;
#pragma unroll
        for (int t = 0; t < 9; t++) {
            int hh = h + t / 3 - 1, ww2 = w + t % 3 - 1;
            if ((unsigned)hh < (unsigned)HH && (unsigned)ww2 < (unsigned)WW)
                acc += xp[hh * WW + ww2] * wn[t];
        }
        float sc = b2g[c] * rsqrtf(b2v[c] + EPSB);
        float v = acc * sc + (b2b[c] - b2m[c] * sc);
        v = v / (1.f + expf(-v));                      // swish
        y[((size_t)b * DIM + c) * HWSZ + p] = v;
    }
}

// ---------------------------------------------------------------------------
__global__ void gap_kernel(const float* __restrict__ y, const float* __restrict__ k,
                           float* __restrict__ gap)
{
    const int c = blockIdx.x, b = blockIdx.y;
    const size_t base = ((size_t)b * DIM + c) * HWSZ;
    float s = 0.f;
    for (int i = threadIdx.x; i < HWSZ; i += blockDim.x)
        s += y[base + i] + k[base + i];
    __shared__ float sh[256];
    sh[threadIdx.x] = s;
    __syncthreads();
    for (int off = 128; off > 0; off >>= 1) {
        if (threadIdx.x < off) sh[threadIdx.x] += sh[threadIdx.x + off];
        __syncthreads();
    }
    if (threadIdx.x == 0) gap[b * DIM + c] = sh[0] / (float)HWSZ;
}

// ---------------------------------------------------------------------------
__global__ void attn_kernel(const float* __restrict__ gap,
                            const float* __restrict__ s1w, const float* __restrict__ s1b,
                            const float* __restrict__ s1g, const float* __restrict__ s1bb,
                            const float* __restrict__ s1m, const float* __restrict__ s1v,
                            const float* __restrict__ s2w, const float* __restrict__ s2b,
                            float* __restrict__ att)
{
    const int b = blockIdx.x;
    const int tid = threadIdx.x;
    __shared__ float sg[DIM];
    __shared__ float sa[ATTN];

    sg[tid] = gap[b * DIM + tid];
    __syncthreads();

    if (tid < ATTN) {
        float d = 0.f;
#pragma unroll 8
        for (int j = 0; j < DIM; j++) d += s1w[tid * DIM + j] * sg[j];
        d += s1b[tid];
        float sc = s1g[tid] * rsqrtf(s1v[tid] + EPSB);
        d = d * sc + (s1bb[tid] - s1m[tid] * sc);
        sa[tid] = fmaxf(d, 0.f);
    }
    __syncthreads();

    float d0 = 0.f, d1 = 0.f;
#pragma unroll 8
    for (int j = 0; j < ATTN; j++) {
        float a = sa[j];
        d0 += s2w[(2 * tid + 0) * ATTN + j] * a;
        d1 += s2w[(2 * tid + 1) * ATTN + j] * a;
    }
    d0 += s2b[2 * tid + 0];
    d1 += s2b[2 * tid + 1];
    float mx = fmaxf(d0, d1);
    float e0 = expf(d0 - mx), e1 = expf(d1 - mx);
    float inv = 1.f / (e0 + e1);
    att[(b * DIM + tid) * 2 + 0] = e0 * inv;
    att[(b * DIM + tid) * 2 + 1] = e1 * inv;
}

// ---------------------------------------------------------------------------
__global__ void out_kernel(const float* __restrict__ y, const float* __restrict__ k,
                           const float* __restrict__ att, float* __restrict__ out)
{
    size_t idx = (size_t)blockIdx.x * blockDim.x + threadIdx.x;
    if (idx >= (size_t)BATCH * DIM * HWSZ) return;
    int bc = (int)(idx / HWSZ);
    float a0 = att[bc * 2 + 0];
    float a1 = att[bc * 2 + 1];
    out[idx] = y[idx] * a0 + k[idx] * a1;
}

// ---------------------------------------------------------------------------
extern "C" void kernel_launch(void* const* d_in, const int* in_sizes, int n_in,
                              void* d_out, int out_size)
{
    const float* x    = (const float*)d_in[0];
    const float* ke_w = (const float*)d_in[1];
    const float* ke_g = (const float*)d_in[2];
    const float* ke_b = (const float*)d_in[3];
    const float* ke_m = (const float*)d_in[4];
    const float* ke_v = (const float*)d_in[5];
    const float* e1_w = (const float*)d_in[6];
    const float* e1_g = (const float*)d_in[7];
    const float* e1_b = (const float*)d_in[8];
    const float* e1_m = (const float*)d_in[9];
    const float* e1_v = (const float*)d_in[10];
    const float* e2_w = (const float*)d_in[11];
    const float* e2_b = (const float*)d_in[12];
    const float* gng  = (const float*)d_in[13];
    const float* gnb  = (const float*)d_in[14];
    const float* c1_w = (const float*)d_in[15];
    const float* c1_g = (const float*)d_in[16];
    const float* c1_b = (const float*)d_in[17];
    const float* c1_m = (const float*)d_in[18];
    const float* c1_v = (const float*)d_in[19];
    const float* b2_g = (const float*)d_in[20];
    const float* b2_b = (const float*)d_in[21];
    const float* b2_m = (const float*)d_in[22];
    const float* b2_v = (const float*)d_in[23];
    const float* s1_w = (const float*)d_in[24];
    const float* s1_b = (const float*)d_in[25];
    const float* s1_g = (const float*)d_in[26];
    const float* s1bb = (const float*)d_in[27];
    const float* s1_m = (const float*)d_in[28];
    const float* s1_v = (const float*)d_in[29];
    const float* s2_w = (const float*)d_in[30];
    const float* s2_b = (const float*)d_in[31];
    float* out = (float*)d_out;

    float *k_, *w1_, *w2_, *xq_, *y_, *gn_, *gap_, *att_;
    cudaGetSymbolAddress((void**)&k_,   g_k);
    cudaGetSymbolAddress((void**)&w1_,  g_w1);
    cudaGetSymbolAddress((void**)&w2_,  g_w2);
    cudaGetSymbolAddress((void**)&xq_,  g_xq);
    cudaGetSymbolAddress((void**)&y_,   g_y);
    cudaGetSymbolAddress((void**)&gn_,  g_gn);
    cudaGetSymbolAddress((void**)&gap_, g_gap);
    cudaGetSymbolAddress((void**)&att_, g_att);

    const int NTILES = (HWSZ + 127) / 128;   // 25

    // 1) key embed: grouped 3x3 conv + BN + ReLU  -> g_k
    convmma<64, 128, 64, 16, 2, 0><<<dim3(4, NTILES, BATCH), 256>>>(
        ke_w, x, nullptr, k_, DIM, 576, DIM, 0, ke_g, ke_b, ke_m, ke_v);

    // 2) w1 = ReLU(BN(e1 . concat(x, k)))  -> g_w1
    convmma<128, 128, 64, 32, 1, 0><<<dim3(1, NTILES, BATCH), 256>>>(
        e1_w, x, k_, w1_, 128, 512, 512, 256, e1_g, e1_b, e1_m, e1_v);

    // 3) w2 = e2 . w1 + bias  -> g_w2
    convmma<128, 128, 64, 32, 0, 2><<<dim3(3, NTILES, BATCH), 256>>>(
        e2_w, w1_, nullptr, w2_, EMB, 128, 128, 0, e2_b, nullptr, nullptr, nullptr);

    // 4) GroupNorm stats
    gn_stats_kernel<<<dim3(GRPS, BATCH), 256>>>(w2_, gn_);

    // 5) xq = BN(c1 . x)  -> g_xq
    convmma<128, 128, 64, 32, 0, 1><<<dim3(2, NTILES, BATCH), 256>>>(
        c1_w, x, nullptr, xq_, DIM, DIM, DIM, 0, c1_g, c1_b, c1_m, c1_v);

    // 6) dynamic conv + BN + swish -> g_y
    dynconv_kernel<<<dim3((HWSZ + 255) / 256, GRPS, BATCH), 256>>>(
        xq_, w2_, gn_, gng, gnb, b2_g, b2_b, b2_m, b2_v, y_);

    // 7) gap = mean(y + k)
    gap_kernel<<<dim3(DIM, BATCH), 256>>>(y_, k_, gap_);

    // 8) split attention
    attn_kernel<<<BATCH, DIM>>>(gap_, s1_w, s1_b, s1_g, s1bb, s1_m, s1_v,
                                s2_w, s2_b, att_);

    // 9) out = y*a0 + k*a1
    size_t total = (size_t)BATCH * DIM * HWSZ;
    out_kernel<<<(unsigned)((total + 255) / 256), 256>>>(y_, k_, att_, out);
}

// round 7
// speedup vs baseline: 2.6477x; 1.1698x over previous
#include <cuda_runtime.h>
#include <cuda_bf16.h>
#include <math.h>
#include <stdint.h>

#define BATCH 16
#define DIM   256
#define HH    56
#define WW    56
#define HWSZ  3136          // 56*56
#define EMB   288
#define ATTN  128
#define GRPS  32            // DIM/SP
#define EPSB  1e-5f
#define BKK   16
#define BNT   112           // 3136 = 28 * 112, no n-edge predicates

// -------------------- scratch (allocation-free: __device__ globals) --------
__device__ float g_k   [(size_t)BATCH * DIM * HWSZ];
__device__ float g_w1  [(size_t)BATCH * 128 * HWSZ];
__device__ float g_w2  [(size_t)BATCH * EMB * HWSZ];
__device__ float g_xq  [(size_t)BATCH * DIM * HWSZ];
__device__ float g_y   [(size_t)BATCH * DIM * HWSZ];
__device__ float g_col [(size_t)BATCH * 4 * 576 * HWSZ];   // im2col for grouped conv
__device__ float g_gn  [BATCH * GRPS * 2];
__device__ float g_gap [BATCH * DIM];
__device__ float g_att [BATCH * DIM * 2];

// ---------------------------------------------------------------------------
__device__ __forceinline__ uint32_t f2tf32(float v) {
    uint32_t u;
    asm("cvt.rna.tf32.f32 %0, %1;" : "=r"(u) : "f"(v));
    return u;
}
__device__ __forceinline__ void mma_tf32(float* c, const uint32_t* a, const uint32_t* b) {
    asm volatile(
        "mma.sync.aligned.m16n8k8.row.col.f32.tf32.tf32.f32 "
        "{%0,%1,%2,%3}, {%4,%5,%6,%7}, {%8,%9}, {%0,%1,%2,%3};\n"
        : "+f"(c[0]), "+f"(c[1]), "+f"(c[2]), "+f"(c[3])
        : "r"(a[0]), "r"(a[1]), "r"(a[2]), "r"(a[3]), "r"(b[0]), "r"(b[1]));
}
__device__ __forceinline__ void cpa16(float* dst, const float* src, bool pred) {
    uint32_t d = (uint32_t)__cvta_generic_to_shared(dst);
    int sz = pred ? 16 : 0;
    asm volatile("cp.async.cg.shared.global [%0], [%1], 16, %2;\n"
                 :: "r"(d), "l"(src), "r"(sz));
}
__device__ __forceinline__ void cp_commit() {
    asm volatile("cp.async.commit_group;\n");
}
template<int N> __device__ __forceinline__ void cp_wait() {
    asm volatile("cp.async.wait_group %0;\n" :: "n"(N));
}

// ---------------------------------------------------------------------------
// Double-buffered cp.async tf32 GEMM:  O[b, m, p] = sum_k W[m,k] * X(b,k,p)
//   MODE 0 : X rows are channels of X1 (XC channels)
//   MODE 1 : concat(X1 [Csplit], X2 [XC-Csplit])
//   MODE 2 : X1 = im2col buffer; B row base = blockIdx.x * 576 (group)
//   EPI  0 : BN + ReLU    EPI 1 : BN    EPI 2 : +bias
// 256 threads = 8 warps, warp grid (BM/WM) x (BN/WN), BK = 16, BN = 112.
// ---------------------------------------------------------------------------
template<int BM, int WM, int WN, int MODE, int EPI>
__global__ void __launch_bounds__(256)
convmma(const float* __restrict__ Wt,
        const float* __restrict__ X1,
        const float* __restrict__ X2,
        float* __restrict__ Out,
        int M, int Ktot, int XC, int Csplit,
        const float* __restrict__ p0,
        const float* __restrict__ p1,
        const float* __restrict__ p2,
        const float* __restrict__ p3)
{
    constexpr int BN = BNT;
    constexpr int WARPS_N = BN / WN;
    constexpr int MT = WM / 16;
    constexpr int NT = WN / 8;
    constexpr int ACH = (BM * BKK) / (4 * 256);   // A 16B-chunks per thread

    const int b    = blockIdx.z;
    const int m0   = blockIdx.x * BM;
    const int n0   = blockIdx.y * BN;
    const int tid  = threadIdx.x;
    const int wid  = tid >> 5;
    const int lane = tid & 31;
    const int grp  = lane >> 2;
    const int tg   = lane & 3;
    const int warp_m = wid / WARPS_N;
    const int warp_n = wid % WARPS_N;

    __shared__ float As[2][BM][20];        // stride 20: conflict-free, 16B aligned
    __shared__ float Bs[2][BKK][BN + 8];   // stride 120: conflict-free, 16B aligned

    float acc[MT][NT][4];
#pragma unroll
    for (int i = 0; i < MT; i++)
#pragma unroll
        for (int j = 0; j < NT; j++)
#pragma unroll
            for (int q = 0; q < 4; q++) acc[i][j][q] = 0.f;

    auto loadA = [&](int s, int k0) {
#pragma unroll
        for (int it = 0; it < ACH; it++) {
            int idx = tid + it * 256;      // over BM * 4 chunks
            int m = idx >> 2, kq = idx & 3;
            int gm = m0 + m;
            cpa16(&As[s][m][kq * 4], Wt + (size_t)gm * Ktot + k0 + kq * 4, gm < M);
        }
    };
    auto loadB = [&](int s, int k0) {
#pragma unroll
        for (int it = 0; it < 2; it++) {
            int idx = tid + it * 256;      // over 16 * 28 = 448 chunks
            if (idx < BKK * (BN / 4)) {
                int kk = idx / (BN / 4);
                int nq = idx % (BN / 4);
                int gk = k0 + kk;
                int gn = n0 + nq * 4;
                const float* src;
                if (MODE == 0)
                    src = X1 + ((size_t)b * XC + gk) * HWSZ + gn;
                else if (MODE == 1)
                    src = (gk < Csplit)
                        ? X1 + ((size_t)b * Csplit + gk) * HWSZ + gn
                        : X2 + ((size_t)b * (XC - Csplit) + (gk - Csplit)) * HWSZ + gn;
                else
                    src = X1 + ((size_t)b * XC + blockIdx.x * 576 + gk) * HWSZ + gn;
                cpa16(&Bs[s][kk][nq * 4], src, true);
            }
        }
    };

    loadA(0, 0); loadB(0, 0); cp_commit();

    const int niter = Ktot / BKK;
    for (int i = 0; i < niter; i++) {
        if (i + 1 < niter) {
            int s = (i + 1) & 1;
            loadA(s, (i + 1) * BKK); loadB(s, (i + 1) * BKK); cp_commit();
            cp_wait<1>();
        } else {
            cp_wait<0>();
        }
        __syncthreads();

        const int s = i & 1;
#pragma unroll
        for (int ks = 0; ks < BKK; ks += 8) {
            uint32_t af[MT][4];
            uint32_t bf[NT][2];
#pragma unroll
            for (int ii = 0; ii < MT; ii++) {
                int m = warp_m * WM + ii * 16 + grp;
                af[ii][0] = f2tf32(As[s][m    ][ks + tg]);
                af[ii][1] = f2tf32(As[s][m + 8][ks + tg]);
                af[ii][2] = f2tf32(As[s][m    ][ks + tg + 4]);
                af[ii][3] = f2tf32(As[s][m + 8][ks + tg + 4]);
            }
#pragma unroll
            for (int j = 0; j < NT; j++) {
                int n = warp_n * WN + j * 8 + grp;
                bf[j][0] = f2tf32(Bs[s][ks + tg    ][n]);
                bf[j][1] = f2tf32(Bs[s][ks + tg + 4][n]);
            }
#pragma unroll
            for (int ii = 0; ii < MT; ii++)
#pragma unroll
                for (int j = 0; j < NT; j++)
                    mma_tf32(acc[ii][j], af[ii], bf[j]);
        }
        __syncthreads();
    }

    // ---- epilogue
#pragma unroll
    for (int i = 0; i < MT; i++) {
        int r0 = m0 + warp_m * WM + i * 16 + grp;
        int r1 = r0 + 8;
        float sc0 = 1.f, sh0 = 0.f, sc1 = 1.f, sh1 = 0.f;
        if (EPI <= 1) {
            if (r0 < M) { sc0 = p0[r0] * rsqrtf(p3[r0] + EPSB); sh0 = p1[r0] - p2[r0] * sc0; }
            if (r1 < M) { sc1 = p0[r1] * rsqrtf(p3[r1] + EPSB); sh1 = p1[r1] - p2[r1] * sc1; }
        } else {
            if (r0 < M) sh0 = p0[r0];
            if (r1 < M) sh1 = p0[r1];
        }
#pragma unroll
        for (int j = 0; j < NT; j++) {
            int n = n0 + warp_n * WN + j * 8 + 2 * tg;
            float v0 = acc[i][j][0] * sc0 + sh0;
            float v1 = acc[i][j][1] * sc0 + sh0;
            float v2 = acc[i][j][2] * sc1 + sh1;
            float v3 = acc[i][j][3] * sc1 + sh1;
            if (EPI == 0) {
                v0 = fmaxf(v0, 0.f); v1 = fmaxf(v1, 0.f);
                v2 = fmaxf(v2, 0.f); v3 = fmaxf(v3, 0.f);
            }
            if (r0 < M) *(float2*)(Out + ((size_t)b * M + r0) * HWSZ + n) = make_float2(v0, v1);
            if (r1 < M) *(float2*)(Out + ((size_t)b * M + r1) * HWSZ + n) = make_float2(v2, v3);
        }
    }
}

// ---------------------------------------------------------------------------
// im2col for grouped 3x3 conv, pad 1: col[b][g*576 + ci*9 + t][p]
// ---------------------------------------------------------------------------
__global__ void im2col_kernel(const float* __restrict__ x, float* __restrict__ col)
{
    const int p = blockIdx.x * 256 + threadIdx.x;
    if (p >= HWSZ) return;
    const int row = blockIdx.y;     // 0..2303
    const int b   = blockIdx.z;
    const int g = row / 576, r = row % 576, ci = r / 9, t = r % 9;
    const int h = p / WW + t / 3 - 1;
    const int w = p % WW + t % 3 - 1;
    float v = 0.f;
    if ((unsigned)h < (unsigned)HH && (unsigned)w < (unsigned)WW)
        v = x[((size_t)b * DIM + g * 64 + ci) * HWSZ + h * WW + w];
    col[((size_t)b * 2304 + row) * HWSZ + p] = v;
}

// ---------------------------------------------------------------------------
__global__ void gn_stats_kernel(const float* __restrict__ w2, float* __restrict__ stat)
{
    const int g = blockIdx.x, b = blockIdx.y;
    const float4* base = (const float4*)(w2 + ((size_t)b * EMB + g * 9) * HWSZ);
    const int n4 = 9 * HWSZ / 4;   // 7056

    float s = 0.f, sq = 0.f;
    for (int i = threadIdx.x; i < n4; i += 512) {
        float4 v = base[i];
        s  += v.x + v.y + v.z + v.w;
        sq += v.x * v.x + v.y * v.y + v.z * v.z + v.w * v.w;
    }
    __shared__ float sh_s[512], sh_q[512];
    sh_s[threadIdx.x] = s; sh_q[threadIdx.x] = sq;
    __syncthreads();
    for (int off = 256; off > 0; off >>= 1) {
        if (threadIdx.x < off) {
            sh_s[threadIdx.x] += sh_s[threadIdx.x + off];
            sh_q[threadIdx.x] += sh_q[threadIdx.x + off];
        }
        __syncthreads();
    }
    if (threadIdx.x == 0) {
        float n = 9.f * HWSZ;
        float mean = sh_s[0] / n;
        float var  = sh_q[0] / n - mean * mean;
        stat[(b * GRPS + g) * 2 + 0] = mean;
        stat[(b * GRPS + g) * 2 + 1] = rsqrtf(var + EPSB);
    }
}

// ---------------------------------------------------------------------------
__global__ void dynconv_kernel(const float* __restrict__ xq,
                               const float* __restrict__ w2,
                               const float* __restrict__ stat,
                               const float* __restrict__ gng,
                               const float* __restrict__ gnb,
                               const float* __restrict__ b2g,
                               const float* __restrict__ b2b,
                               const float* __restrict__ b2m,
                               const float* __restrict__ b2v,
                               float* __restrict__ y)
{
    const int b = blockIdx.z, g = blockIdx.y;
    const int p = blockIdx.x * blockDim.x + threadIdx.x;
    if (p >= HWSZ) return;
    const int h = p / WW, w = p % WW;

    const float mean = stat[(b * GRPS + g) * 2 + 0];
    const float rstd = stat[(b * GRPS + g) * 2 + 1];

    float wn[9];
#pragma unroll
    for (int t = 0; t < 9; t++) {
        int ch = g * 9 + t;
        float v = w2[((size_t)b * EMB + ch) * HWSZ + p];
        wn[t] = (v - mean) * rstd * gng[ch] + gnb[ch];
    }

#pragma unroll
    for (int s = 0; s < 8; s++) {
        int c = g * 8 + s;
        const float* xp = xq + ((size_t)b * DIM + c) * HWSZ;
        float acc = 0.f;
#pragma unroll
        for (int t = 0; t < 9; t++) {
            int hh = h + t / 3 - 1, ww2 = w + t % 3 - 1;
            if ((unsigned)hh < (unsigned)HH && (unsigned)ww2 < (unsigned)WW)
                acc += xp[hh * WW + ww2] * wn[t];
        }
        float sc = b2g[c] * rsqrtf(b2v[c] + EPSB);
        float v = acc * sc + (b2b[c] - b2m[c] * sc);
        v = v / (1.f + expf(-v));
        y[((size_t)b * DIM + c) * HWSZ + p] = v;
    }
}

// ---------------------------------------------------------------------------
__global__ void gap_kernel(const float* __restrict__ y, const float* __restrict__ k,
                           float* __restrict__ gap)
{
    const int c = blockIdx.x, b = blockIdx.y;
    const size_t base = ((size_t)b * DIM + c) * HWSZ;
    float s = 0.f;
    for (int i = threadIdx.x; i < HWSZ; i += blockDim.x)
        s += y[base + i] + k[base + i];
    __shared__ float sh[256];
    sh[threadIdx.x] = s;
    __syncthreads();
    for (int off = 128; off > 0; off >>= 1) {
        if (threadIdx.x < off) sh[threadIdx.x] += sh[threadIdx.x + off];
        __syncthreads();
    }
    if (threadIdx.x == 0) gap[b * DIM + c] = sh[0] / (float)HWSZ;
}

// ---------------------------------------------------------------------------
__global__ void attn_kernel(const float* __restrict__ gap,
                            const float* __restrict__ s1w, const float* __restrict__ s1b,
                            const float* __restrict__ s1g, const float* __restrict__ s1bb,
                            const float* __restrict__ s1m, const float* __restrict__ s1v,
                            const float* __restrict__ s2w, const float* __restrict__ s2b,
                            float* __restrict__ att)
{
    const int b = blockIdx.x;
    const int tid = threadIdx.x;
    __shared__ float sg[DIM];
    __shared__ float sa[ATTN];

    sg[tid] = gap[b * DIM + tid];
    __syncthreads();

    if (tid < ATTN) {
        float d = 0.f;
#pragma unroll 8
        for (int j = 0; j < DIM; j++) d += s1w[tid * DIM + j] * sg[j];
        d += s1b[tid];
        float sc = s1g[tid] * rsqrtf(s1v[tid] + EPSB);
        d = d * sc + (s1bb[tid] - s1m[tid] * sc);
        sa[tid] = fmaxf(d, 0.f);
    }
    __syncthreads();

    float d0 = 0.f, d1 = 0.f;
#pragma unroll 8
    for (int j = 0; j < ATTN; j++) {
        float a = sa[j];
        d0 += s2w[(2 * tid + 0) * ATTN + j] * a;
        d1 += s2w[(2 * tid + 1) * ATTN + j] * a;
    }
    d0 += s2b[2 * tid + 0];
    d1 += s2b[2 * tid + 1];
    float mx = fmaxf(d0, d1);
    float e0 = expf(d0 - mx), e1 = expf(d1 - mx);
    float inv = 1.f / (e0 + e1);
    att[(b * DIM + tid) * 2 + 0] = e0 * inv;
    att[(b * DIM + tid) * 2 + 1] = e1 * inv;
}

// ---------------------------------------------------------------------------
__global__ void out_kernel(const float* __restrict__ y, const float* __restrict__ k,
                           const float* __restrict__ att, float* __restrict__ out)
{
    size_t i4 = (size_t)blockIdx.x * blockDim.x + threadIdx.x;
    if (i4 >= (size_t)BATCH * DIM * HWSZ / 4) return;
    int bc = (int)(i4 * 4 / HWSZ);
    float a0 = att[bc * 2 + 0];
    float a1 = att[bc * 2 + 1];
    float4 yv = ((const float4*)y)[i4];
    float4 kv = ((const float4*)k)[i4];
    float4 o;
    o.x = yv.x * a0 + kv.x * a1;
    o.y = yv.y * a0 + kv.y * a1;
    o.z = yv.z * a0 + kv.z * a1;
    o.w = yv.w * a0 + kv.w * a1;
    ((float4*)out)[i4] = o;
}

// ---------------------------------------------------------------------------
extern "C" void kernel_launch(void* const* d_in, const int* in_sizes, int n_in,
                              void* d_out, int out_size)
{
    const float* x    = (const float*)d_in[0];
    const float* ke_w = (const float*)d_in[1];
    const float* ke_g = (const float*)d_in[2];
    const float* ke_b = (const float*)d_in[3];
    const float* ke_m = (const float*)d_in[4];
    const float* ke_v = (const float*)d_in[5];
    const float* e1_w = (const float*)d_in[6];
    const float* e1_g = (const float*)d_in[7];
    const float* e1_b = (const float*)d_in[8];
    const float* e1_m = (const float*)d_in[9];
    const float* e1_v = (const float*)d_in[10];
    const float* e2_w = (const float*)d_in[11];
    const float* e2_b = (const float*)d_in[12];
    const float* gng  = (const float*)d_in[13];
    const float* gnb  = (const float*)d_in[14];
    const float* c1_w = (const float*)d_in[15];
    const float* c1_g = (const float*)d_in[16];
    const float* c1_b = (const float*)d_in[17];
    const float* c1_m = (const float*)d_in[18];
    const float* c1_v = (const float*)d_in[19];
    const float* b2_g = (const float*)d_in[20];
    const float* b2_b = (const float*)d_in[21];
    const float* b2_m = (const float*)d_in[22];
    const float* b2_v = (const float*)d_in[23];
    const float* s1_w = (const float*)d_in[24];
    const float* s1_b = (const float*)d_in[25];
    const float* s1_g = (const float*)d_in[26];
    const float* s1bb = (const float*)d_in[27];
    const float* s1_m = (const float*)d_in[28];
    const float* s1_v = (const float*)d_in[29];
    const float* s2_w = (const float*)d_in[30];
    const float* s2_b = (const float*)d_in[31];
    float* out = (float*)d_out;

    float *k_, *w1_, *w2_, *xq_, *y_, *col_, *gn_, *gap_, *att_;
    cudaGetSymbolAddress((void**)&k_,   g_k);
    cudaGetSymbolAddress((void**)&w1_,  g_w1);
    cudaGetSymbolAddress((void**)&w2_,  g_w2);
    cudaGetSymbolAddress((void**)&xq_,  g_xq);
    cudaGetSymbolAddress((void**)&y_,   g_y);
    cudaGetSymbolAddress((void**)&col_, g_col);
    cudaGetSymbolAddress((void**)&gn_,  g_gn);
    cudaGetSymbolAddress((void**)&gap_, g_gap);
    cudaGetSymbolAddress((void**)&att_, g_att);

    const int NTILES = HWSZ / BNT;   // 28

    // 0) im2col for grouped conv
    im2col_kernel<<<dim3((HWSZ + 255) / 256, 2304, BATCH), 256>>>(x, col_);

    // 1) key embed: grouped 3x3 conv + BN + ReLU  (BM=64 per group)
    convmma<64, 16, 56, 2, 0><<<dim3(4, NTILES, BATCH), 256>>>(
        ke_w, col_, nullptr, k_, DIM, 576, 2304, 0, ke_g, ke_b, ke_m, ke_v);

    // 2) w1 = ReLU(BN(e1 . concat(x, k)))
    convmma<128, 32, 56, 1, 0><<<dim3(1, NTILES, BATCH), 256>>>(
        e1_w, x, k_, w1_, 128, 512, 512, 256, e1_g, e1_b, e1_m, e1_v);

    // 3) w2 = e2 . w1 + bias
    convmma<128, 32, 56, 0, 2><<<dim3(3, NTILES, BATCH), 256>>>(
        e2_w, w1_, nullptr, w2_, EMB, 128, 128, 0, e2_b, nullptr, nullptr, nullptr);

    // 4) GroupNorm stats
    gn_stats_kernel<<<dim3(GRPS, BATCH), 512>>>(w2_, gn_);

    // 5) xq = BN(c1 . x)
    convmma<128, 32, 56, 0, 1><<<dim3(2, NTILES, BATCH), 256>>>(
        c1_w, x, nullptr, xq_, DIM, DIM, DIM, 0, c1_g, c1_b, c1_m, c1_v);

    // 6) dynamic conv + BN + swish
    dynconv_kernel<<<dim3((HWSZ + 255) / 256, GRPS, BATCH), 256>>>(
        xq_, w2_, gn_, gng, gnb, b2_g, b2_b, b2_m, b2_v, y_);

    // 7) gap = mean(y + k)
    gap_kernel<<<dim3(DIM, BATCH), 256>>>(y_, k_, gap_);

    // 8) split attention
    attn_kernel<<<BATCH, DIM>>>(gap_, s1_w, s1_b, s1_g, s1bb, s1_m, s1_v,
                                s2_w, s2_b, att_);

    // 9) out = y*a0 + k*a1
    size_t total4 = (size_t)BATCH * DIM * HWSZ / 4;
    out_kernel<<<(unsigned)((total4 + 255) / 256), 256>>>(y_, k_, att_, out);
}